// round 2
// baseline (speedup 1.0000x reference)
#include <cuda_runtime.h>
#include <math.h>

#define BATCH 128
#define SEQT  1024
#define NSTEP 1023
#define IND   256
#define HID   1024
#define OUTD  128

#define MT 64
#define JT 16
#define KT 16
#define NBLK 128   // persistent grid: (2, 64)

// Scratch (device globals — allocation inside kernel_launch is forbidden).
__device__ float    g_hall[(size_t)NSTEP * BATCH * HID];   // all h_t (~536 MB)
__device__ unsigned g_bar;                                  // grid barrier counter

// Replay-safe grid barrier: epoch arithmetic on a monotonic counter.
// Every barrier consumes exactly NBLK increments, so epochs stay aligned
// across graph replays with no reset needed.
__device__ __forceinline__ void grid_barrier()
{
    __syncthreads();
    if (threadIdx.x == 0) {
        __threadfence();
        unsigned old    = atomicAdd(&g_bar, 1u);
        unsigned target = (old / NBLK + 1u) * NBLK;
        unsigned cur;
        do {
            asm volatile("ld.acquire.gpu.u32 %0, [%1];" : "=r"(cur) : "l"(&g_bar));
        } while (cur < target);
    }
    __syncthreads();
}

// ---------------------------------------------------------------------------
// Persistent LSTM: one launch, 1023 steps, software grid sync between steps.
// grid = (2, 64): blockIdx.x tiles batch (64 rows), blockIdx.y tiles hidden
// units (16 units -> 64 gate columns: n = j_local*4 + gate).
// Cell state c lives in registers for the whole sequence.
// ---------------------------------------------------------------------------
__global__ __launch_bounds__(256) void lstm_persistent_kernel(
    const float* __restrict__ seq,
    const float* __restrict__ Wih,
    const float* __restrict__ Whh,
    const float* __restrict__ bih,
    const float* __restrict__ bhh)
{
    __shared__ float As[KT][MT + 4];
    __shared__ float Bs[KT][MT + 4];

    const int tid = threadIdx.x;
    const int tx  = tid & 15;
    const int ty  = tid >> 4;
    const int m0  = blockIdx.x * MT;
    const int j0  = blockIdx.y * JT;

    // loader mapping: 256 threads cover a 64x16 tile as 64 rows x 4 float4s
    const int lr = tid >> 2;          // 0..63 tile row
    const int lk = (tid & 3) * 4;     // 0,4,8,12

    // B-loader: tile column n = lr maps to weight row g*HID + j0 + j_local,
    // with n = j_local*4 + g.
    const int wrow = (lr & 3) * HID + j0 + (lr >> 2);

    // Per-thread fixed row pointers
    const float* a_seq  = seq + (size_t)(m0 + lr) * SEQT * IND;   // + t*IND
    const float* b_ihp  = Wih + (size_t)wrow * IND;
    const float* b_hhp  = Whh + (size_t)wrow * HID;
    const size_t a_hoff = (size_t)(m0 + lr) * HID;

    // Fused biases + register-resident cell state (4 batch rows x 1 unit)
    const int j = j0 + tx;
    const float bb0 = bih[0 * HID + j] + bhh[0 * HID + j];
    const float bb1 = bih[1 * HID + j] + bhh[1 * HID + j];
    const float bb2 = bih[2 * HID + j] + bhh[2 * HID + j];
    const float bb3 = bih[3 * HID + j] + bhh[3 * HID + j];
    float c[4] = {0.f, 0.f, 0.f, 0.f};

    for (int t = 0; t < NSTEP; t++) {
        float acc[4][4];
#pragma unroll
        for (int i = 0; i < 4; i++)
#pragma unroll
            for (int jj = 0; jj < 4; jj++) acc[i][jj] = 0.f;

        // ---------------- phase A: x_t @ W_ih^T  (K = 256) ----------------
        {
            const float* ap = a_seq + (size_t)t * IND;
            float4 ga = *(const float4*)(ap + lk);
            float4 gb = *(const float4*)(b_ihp + lk);
            for (int k0 = 0; k0 < IND; k0 += KT) {
                As[lk + 0][lr] = ga.x; As[lk + 1][lr] = ga.y;
                As[lk + 2][lr] = ga.z; As[lk + 3][lr] = ga.w;
                Bs[lk + 0][lr] = gb.x; Bs[lk + 1][lr] = gb.y;
                Bs[lk + 2][lr] = gb.z; Bs[lk + 3][lr] = gb.w;
                __syncthreads();
                if (k0 + KT < IND) {                       // prefetch next tile
                    ga = *(const float4*)(ap + k0 + KT + lk);
                    gb = *(const float4*)(b_ihp + k0 + KT + lk);
                }
#pragma unroll
                for (int k = 0; k < KT; k++) {
                    float4 a = *(const float4*)&As[k][ty * 4];
                    float4 b = *(const float4*)&Bs[k][tx * 4];
                    acc[0][0] += a.x * b.x; acc[0][1] += a.x * b.y;
                    acc[0][2] += a.x * b.z; acc[0][3] += a.x * b.w;
                    acc[1][0] += a.y * b.x; acc[1][1] += a.y * b.y;
                    acc[1][2] += a.y * b.z; acc[1][3] += a.y * b.w;
                    acc[2][0] += a.z * b.x; acc[2][1] += a.z * b.y;
                    acc[2][2] += a.z * b.z; acc[2][3] += a.z * b.w;
                    acc[3][0] += a.w * b.x; acc[3][1] += a.w * b.y;
                    acc[3][2] += a.w * b.z; acc[3][3] += a.w * b.w;
                }
                __syncthreads();
            }
        }

        // ---------------- phase B: h_{t-1} @ W_hh^T  (K = 1024) -----------
        if (t > 0) {
            const float* ap = g_hall + (size_t)(t - 1) * BATCH * HID + a_hoff;
            float4 ga = *(const float4*)(ap + lk);
            float4 gb = *(const float4*)(b_hhp + lk);
            for (int k0 = 0; k0 < HID; k0 += KT) {
                As[lk + 0][lr] = ga.x; As[lk + 1][lr] = ga.y;
                As[lk + 2][lr] = ga.z; As[lk + 3][lr] = ga.w;
                Bs[lk + 0][lr] = gb.x; Bs[lk + 1][lr] = gb.y;
                Bs[lk + 2][lr] = gb.z; Bs[lk + 3][lr] = gb.w;
                __syncthreads();
                if (k0 + KT < HID) {                       // prefetch next tile
                    ga = *(const float4*)(ap + k0 + KT + lk);
                    gb = *(const float4*)(b_hhp + k0 + KT + lk);
                }
#pragma unroll
                for (int k = 0; k < KT; k++) {
                    float4 a = *(const float4*)&As[k][ty * 4];
                    float4 b = *(const float4*)&Bs[k][tx * 4];
                    acc[0][0] += a.x * b.x; acc[0][1] += a.x * b.y;
                    acc[0][2] += a.x * b.z; acc[0][3] += a.x * b.w;
                    acc[1][0] += a.y * b.x; acc[1][1] += a.y * b.y;
                    acc[1][2] += a.y * b.z; acc[1][3] += a.y * b.w;
                    acc[2][0] += a.z * b.x; acc[2][1] += a.z * b.y;
                    acc[2][2] += a.z * b.z; acc[2][3] += a.z * b.w;
                    acc[3][0] += a.w * b.x; acc[3][1] += a.w * b.y;
                    acc[3][2] += a.w * b.z; acc[3][3] += a.w * b.w;
                }
                __syncthreads();
            }
        }

        // ---------------- pointwise LSTM cell update ----------------
        float* hout = g_hall + (size_t)t * BATCH * HID;
#pragma unroll
        for (int i = 0; i < 4; i++) {
            const int b = m0 + ty * 4 + i;
            const float gi = acc[i][0] + bb0;
            const float gf = acc[i][1] + bb1;
            const float gg = acc[i][2] + bb2;
            const float go = acc[i][3] + bb3;
            const float si = 1.f / (1.f + expf(-gi));
            const float sf = 1.f / (1.f + expf(-gf));
            const float tg = tanhf(gg);
            const float so = 1.f / (1.f + expf(-go));
            const float cn = sf * c[i] + si * tg;
            c[i] = cn;
            hout[(size_t)b * HID + j] = so * tanhf(cn);
        }

        // h_t visible to all blocks before anyone starts step t+1
        grid_barrier();
    }
}

// ---------------------------------------------------------------------------
// Head GEMM: logits[t][b][v] = h_t[b] . W_out[v] + b_out[v], one block per t.
// ---------------------------------------------------------------------------
__global__ __launch_bounds__(256) void head_kernel(
    const float* __restrict__ Wout,
    const float* __restrict__ bout,
    float* __restrict__ out)
{
    const int t = blockIdx.x;
    __shared__ float As[8][OUTD + 4];
    __shared__ float Bs[8][OUTD + 4];

    const int tid = threadIdx.x;
    const int tx  = tid & 15;
    const int ty  = tid >> 4;
    const int lr  = tid >> 1;           // 0..127
    const int lk  = (tid & 1) * 4;      // 0 or 4

    const float* hptr = g_hall + (size_t)t * BATCH * HID;

    float acc[8][8];
#pragma unroll
    for (int i = 0; i < 8; i++)
#pragma unroll
        for (int j = 0; j < 8; j++) acc[i][j] = 0.f;

    for (int k0 = 0; k0 < HID; k0 += 8) {
        float4 av = *(const float4*)(hptr + (size_t)lr * HID + k0 + lk);
        float4 bv = *(const float4*)(Wout + (size_t)lr * HID + k0 + lk);
        As[lk + 0][lr] = av.x; As[lk + 1][lr] = av.y;
        As[lk + 2][lr] = av.z; As[lk + 3][lr] = av.w;
        Bs[lk + 0][lr] = bv.x; Bs[lk + 1][lr] = bv.y;
        Bs[lk + 2][lr] = bv.z; Bs[lk + 3][lr] = bv.w;
        __syncthreads();
#pragma unroll
        for (int k = 0; k < 8; k++) {
            float a[8], bb[8];
            *(float4*)&a[0]  = *(const float4*)&As[k][ty * 8];
            *(float4*)&a[4]  = *(const float4*)&As[k][ty * 8 + 4];
            *(float4*)&bb[0] = *(const float4*)&Bs[k][tx * 8];
            *(float4*)&bb[4] = *(const float4*)&Bs[k][tx * 8 + 4];
#pragma unroll
            for (int i = 0; i < 8; i++)
#pragma unroll
                for (int j = 0; j < 8; j++) acc[i][j] += a[i] * bb[j];
        }
        __syncthreads();
    }

#pragma unroll
    for (int i = 0; i < 8; i++) {
        const int b = ty * 8 + i;
        float* orow = out + ((size_t)b * NSTEP + t) * OUTD;
#pragma unroll
        for (int j = 0; j < 8; j++) {
            const int v = tx * 8 + j;
            orow[v] = acc[i][j] + bout[v];
        }
    }
}

// ---------------------------------------------------------------------------
// In-place log-softmax: one warp per 128-wide row (4 floats per lane).
// ---------------------------------------------------------------------------
__global__ __launch_bounds__(256) void lsm_kernel(float* __restrict__ out)
{
    const int row  = (blockIdx.x * 256 + threadIdx.x) >> 5;
    const int lane = threadIdx.x & 31;
    float* p = out + (size_t)row * OUTD;

    float4 v = ((float4*)p)[lane];
    float m = fmaxf(fmaxf(v.x, v.y), fmaxf(v.z, v.w));
#pragma unroll
    for (int o = 16; o > 0; o >>= 1)
        m = fmaxf(m, __shfl_xor_sync(0xffffffffu, m, o));
    float s = expf(v.x - m) + expf(v.y - m) + expf(v.z - m) + expf(v.w - m);
#pragma unroll
    for (int o = 16; o > 0; o >>= 1)
        s += __shfl_xor_sync(0xffffffffu, s, o);
    const float lse = m + logf(s);
    v.x -= lse; v.y -= lse; v.z -= lse; v.w -= lse;
    ((float4*)p)[lane] = v;
}

// ---------------------------------------------------------------------------
extern "C" void kernel_launch(void* const* d_in, const int* in_sizes, int n_in,
                              void* d_out, int out_size)
{
    const float* seq  = (const float*)d_in[0];   // [128, 1024, 256]
    const float* Wih  = (const float*)d_in[1];   // [4096, 256]
    const float* Whh  = (const float*)d_in[2];   // [4096, 1024]
    const float* bih  = (const float*)d_in[3];   // [4096]
    const float* bhh  = (const float*)d_in[4];   // [4096]
    const float* Wout = (const float*)d_in[5];   // [128, 1024]
    const float* bout = (const float*)d_in[6];   // [128]
    float* out = (float*)d_out;                  // [128, 1023, 128]

    dim3 sgrid(BATCH / MT, HID / JT);            // (2, 64) = 128 resident blocks
    lstm_persistent_kernel<<<sgrid, 256>>>(seq, Wih, Whh, bih, bhh);

    head_kernel<<<NSTEP, 256>>>(Wout, bout, out);

    lsm_kernel<<<(BATCH * NSTEP) / 8, 256>>>(out);
}

// round 4
// speedup vs baseline: 1.7683x; 1.7683x over previous
#include <cuda_runtime.h>
#include <math.h>
#include <stdint.h>

#define BATCH 128
#define SEQT  1024
#define NSTEP 1023
#define IND   256
#define HID   1024
#define OUTD  128

#define NCTA    128        // persistent grid; CTA n owns hidden units [8n, 8n+8)
#define THREADS 256        // 8 warps
#define NCHUNK  160        // K chunks of 8 (K total = 256 + 1024 = 1280)
#define NSTAGE   40        // stages of 32 K
#define NSTAGE_X  8        // x-only stages (K=256)
#define AS       36        // A-tile row stride in floats (36 % 32 == 4 -> conflict-free)

// SMEM: [B fragments 160KB][A stage buf0 18KB][A stage buf1 18KB]
#define SMB_FLOATS (NCHUNK * 4 * 64)      // 40960 floats = 160KB
#define SMA_FLOATS (128 * AS)             // 4608 floats per stage buffer
#define SM_TOTAL   ((SMB_FLOATS + 2 * SMA_FLOATS) * 4)   // 200704 bytes

// Scratch (device globals — allocation inside kernel_launch is forbidden).
__device__ float    g_hall[(size_t)NSTEP * BATCH * HID];   // all h_t (~536 MB)
__device__ unsigned g_bar;                                  // grid barrier counter

// ---------------------------------------------------------------------------
__device__ __forceinline__ uint32_t f2tf32(float x) {   // round-to-nearest tf32
    uint32_t r;
    asm("cvt.rna.tf32.f32 %0, %1;" : "=r"(r) : "f"(x));
    return r;
}

// D[16,8] += A[16,8] * B[8,8]  (tf32, f32 accum), legacy mma.sync (compute_103 baseline)
__device__ __forceinline__ void mma_tf32(float* d,
                                         uint32_t a0, uint32_t a1, uint32_t a2, uint32_t a3,
                                         uint32_t b0, uint32_t b1)
{
    asm volatile(
        "mma.sync.aligned.m16n8k8.row.col.f32.tf32.tf32.f32 "
        "{%0,%1,%2,%3}, {%4,%5,%6,%7}, {%8,%9}, {%0,%1,%2,%3};"
        : "+f"(d[0]), "+f"(d[1]), "+f"(d[2]), "+f"(d[3])
        : "r"(a0), "r"(a1), "r"(a2), "r"(a3), "r"(b0), "r"(b1));
}

// Replay-safe grid barrier (monotonic epoch counter; validated in round 2).
__device__ __forceinline__ void grid_barrier()
{
    __syncthreads();
    if (threadIdx.x == 0) {
        __threadfence();
        unsigned old    = atomicAdd(&g_bar, 1u);
        unsigned target = (old / NCTA + 1u) * NCTA;
        unsigned cur;
        do {
            asm volatile("ld.acquire.gpu.u32 %0, [%1];" : "=r"(cur) : "l"(&g_bar));
        } while (cur < target);
    }
    __syncthreads();
}

// ---------------------------------------------------------------------------
// Persistent tf32 tensor-core LSTM (mma.sync).
// B (weights) resident in SMEM in fragment order:
//   chunk c (0..159), n-tile nt (= gate 0..3): 64 floats, lane L holds
//   b0 = W[gate*H + 8*cta + (L>>2)][c*8 + (L&3)], b1 = same +4 in k,
//   stored interleaved as float2 at Bs[(c*4+nt)*64 + L*2].
// A staged per 32-K stage, row-major, row stride AS=36 (conflict-free).
// Warp w computes batch rows [16w,16w+16) x all 32 gate cols.
// ---------------------------------------------------------------------------
__global__ __launch_bounds__(THREADS, 1) void lstm_tc_kernel(
    const float* __restrict__ seq,
    const float* __restrict__ Wih,
    const float* __restrict__ Whh,
    const float* __restrict__ bih,
    const float* __restrict__ bhh)
{
    extern __shared__ float smem[];
    float* Bs = smem;
    float* As = smem + SMB_FLOATS;

    const int tid  = threadIdx.x;
    const int wid  = tid >> 5;
    const int lane = tid & 31;
    const int cta  = blockIdx.x;

    // ---- stage resident weights into fragment order (once) ----
    for (int idx = tid; idx < NCHUNK * 4 * 32; idx += THREADS) {
        const int c  = idx >> 7;            // chunk 0..159
        const int nt = (idx >> 5) & 3;      // gate
        const int ln = idx & 31;
        const int u  = ln >> 2;
        const int k  = ln & 3;
        const int wr = nt * HID + 8 * cta + u;
        float v0, v1;
        if (c < 32) {
            const float* p = Wih + (size_t)wr * IND + c * 8 + k;
            v0 = p[0]; v1 = p[4];
        } else {
            const float* p = Whh + (size_t)wr * HID + (c - 32) * 8 + k;
            v0 = p[0]; v1 = p[4];
        }
        Bs[(c * 4 + nt) * 64 + ln * 2 + 0] = __uint_as_float(f2tf32(v0));
        Bs[(c * 4 + nt) * 64 + ln * 2 + 1] = __uint_as_float(f2tf32(v1));
    }

    // ---- per-thread fused biases: this thread's 2 units x 4 gates ----
    // Thread owns D cols (lane&3)*2 and +1 -> local units u0=2m, u1=2m+1.
    const int m  = lane & 3;
    float bI[2], bF[2], bG[2], bO[2];
#pragma unroll
    for (int e = 0; e < 2; e++) {
        const int j = 8 * cta + 2 * m + e;
        bI[e] = bih[0 * HID + j] + bhh[0 * HID + j];
        bF[e] = bih[1 * HID + j] + bhh[1 * HID + j];
        bG[e] = bih[2 * HID + j] + bhh[2 * HID + j];
        bO[e] = bih[3 * HID + j] + bhh[3 * HID + j];
    }
    // Cell state: j=0:(r0,u0) 1:(r0,u1) 2:(r0+8,u0) 3:(r0+8,u1)
    float cst[4] = {0.f, 0.f, 0.f, 0.f};

    const int r0 = wid * 16 + (lane >> 2);
    __syncthreads();

    for (int t = 0; t < NSTEP; t++) {
        const int nst = (t == 0) ? NSTAGE_X : NSTAGE;

        float acc[4][4];
#pragma unroll
        for (int nt = 0; nt < 4; nt++)
#pragma unroll
            for (int j = 0; j < 4; j++) acc[nt][j] = 0.f;

        // prologue: stage 0
        float4 r[4];
#pragma unroll
        for (int i = 0; i < 4; i++) {
            const int idx = i * THREADS + tid;
            const int row = idx >> 3, q = idx & 7;
            r[i] = *(const float4*)(seq + (size_t)row * (SEQT * IND)
                                        + (size_t)t * IND + q * 4);
        }
#pragma unroll
        for (int i = 0; i < 4; i++) {
            const int idx = i * THREADS + tid;
            const int row = idx >> 3, q = idx & 7;
            *(float4*)(As + row * AS + q * 4) = make_float4(
                __uint_as_float(f2tf32(r[i].x)), __uint_as_float(f2tf32(r[i].y)),
                __uint_as_float(f2tf32(r[i].z)), __uint_as_float(f2tf32(r[i].w)));
        }
        __syncthreads();

        for (int s = 0; s < nst; s++) {
            // prefetch next stage from global
            float4 rn[4];
            if (s + 1 < nst) {
                const int sn = s + 1;
#pragma unroll
                for (int i = 0; i < 4; i++) {
                    const int idx = i * THREADS + tid;
                    const int row = idx >> 3, q = idx & 7;
                    const float* p = (sn < NSTAGE_X)
                        ? seq + (size_t)row * (SEQT * IND) + (size_t)t * IND + sn * 32 + q * 4
                        : g_hall + (size_t)(t - 1) * BATCH * HID + (size_t)row * HID
                                 + (sn - NSTAGE_X) * 32 + q * 4;
                    rn[i] = *(const float4*)p;
                }
            }

            // compute current stage (4 chunks x 4 n-tiles)
            const float* Ab = As + (s & 1) * SMA_FLOATS;
            const int cbase = s * 4;
#pragma unroll
            for (int cc = 0; cc < 4; cc++) {
                const int ak = cc * 8 + (lane & 3);
                const uint32_t a0 = __float_as_uint(Ab[(r0)     * AS + ak]);
                const uint32_t a1 = __float_as_uint(Ab[(r0 + 8) * AS + ak]);
                const uint32_t a2 = __float_as_uint(Ab[(r0)     * AS + ak + 4]);
                const uint32_t a3 = __float_as_uint(Ab[(r0 + 8) * AS + ak + 4]);
#pragma unroll
                for (int nt = 0; nt < 4; nt++) {
                    const float2 b = *(const float2*)&Bs[((cbase + cc) * 4 + nt) * 64 + lane * 2];
                    mma_tf32(acc[nt], a0, a1, a2, a3,
                             __float_as_uint(b.x), __float_as_uint(b.y));
                }
            }

            // store prefetched stage into the other buffer
            if (s + 1 < nst) {
                float* An = As + ((s + 1) & 1) * SMA_FLOATS;
#pragma unroll
                for (int i = 0; i < 4; i++) {
                    const int idx = i * THREADS + tid;
                    const int row = idx >> 3, q = idx & 7;
                    *(float4*)(An + row * AS + q * 4) = make_float4(
                        __uint_as_float(f2tf32(rn[i].x)), __uint_as_float(f2tf32(rn[i].y)),
                        __uint_as_float(f2tf32(rn[i].z)), __uint_as_float(f2tf32(rn[i].w)));
                }
            }
            __syncthreads();
        }

        // ---- cell update: thread-local, gates = acc[gate][j] ----
        float* hp = g_hall + (size_t)t * BATCH * HID;
#pragma unroll
        for (int j = 0; j < 4; j++) {
            const int row = r0 + (j >> 1) * 8;
            const int e   = j & 1;
            const float gi = acc[0][j] + bI[e];
            const float gf = acc[1][j] + bF[e];
            const float gg = acc[2][j] + bG[e];
            const float go = acc[3][j] + bO[e];
            const float si = 1.f / (1.f + expf(-gi));
            const float sf = 1.f / (1.f + expf(-gf));
            const float tg = tanhf(gg);
            const float so = 1.f / (1.f + expf(-go));
            const float cn = sf * cst[j] + si * tg;
            cst[j] = cn;
            hp[(size_t)row * HID + 8 * cta + 2 * m + e] = so * tanhf(cn);
        }

        grid_barrier();   // h_t visible everywhere before step t+1
    }
}

// ---------------------------------------------------------------------------
// Head GEMM: logits[t][b][v] = h_t[b] . W_out[v] + b_out[v], one block per t.
// ---------------------------------------------------------------------------
__global__ __launch_bounds__(256) void head_kernel(
    const float* __restrict__ Wout,
    const float* __restrict__ bout,
    float* __restrict__ out)
{
    const int t = blockIdx.x;
    __shared__ float As[8][OUTD + 4];
    __shared__ float Bs[8][OUTD + 4];

    const int tid = threadIdx.x;
    const int tx  = tid & 15;
    const int ty  = tid >> 4;
    const int lr  = tid >> 1;
    const int lk  = (tid & 1) * 4;

    const float* hptr = g_hall + (size_t)t * BATCH * HID;

    float acc[8][8];
#pragma unroll
    for (int i = 0; i < 8; i++)
#pragma unroll
        for (int j = 0; j < 8; j++) acc[i][j] = 0.f;

    for (int k0 = 0; k0 < HID; k0 += 8) {
        float4 av = *(const float4*)(hptr + (size_t)lr * HID + k0 + lk);
        float4 bv = *(const float4*)(Wout + (size_t)lr * HID + k0 + lk);
        As[lk + 0][lr] = av.x; As[lk + 1][lr] = av.y;
        As[lk + 2][lr] = av.z; As[lk + 3][lr] = av.w;
        Bs[lk + 0][lr] = bv.x; Bs[lk + 1][lr] = bv.y;
        Bs[lk + 2][lr] = bv.z; Bs[lk + 3][lr] = bv.w;
        __syncthreads();
#pragma unroll
        for (int k = 0; k < 8; k++) {
            float a[8], bb[8];
            *(float4*)&a[0]  = *(const float4*)&As[k][ty * 8];
            *(float4*)&a[4]  = *(const float4*)&As[k][ty * 8 + 4];
            *(float4*)&bb[0] = *(const float4*)&Bs[k][tx * 8];
            *(float4*)&bb[4] = *(const float4*)&Bs[k][tx * 8 + 4];
#pragma unroll
            for (int i = 0; i < 8; i++)
#pragma unroll
                for (int j = 0; j < 8; j++) acc[i][j] += a[i] * bb[j];
        }
        __syncthreads();
    }

#pragma unroll
    for (int i = 0; i < 8; i++) {
        const int b = ty * 8 + i;
        float* orow = out + ((size_t)b * NSTEP + t) * OUTD;
#pragma unroll
        for (int j = 0; j < 8; j++) {
            const int v = tx * 8 + j;
            orow[v] = acc[i][j] + bout[v];
        }
    }
}

// ---------------------------------------------------------------------------
// In-place log-softmax: one warp per 128-wide row.
// ---------------------------------------------------------------------------
__global__ __launch_bounds__(256) void lsm_kernel(float* __restrict__ out)
{
    const int row  = (blockIdx.x * 256 + threadIdx.x) >> 5;
    const int lane = threadIdx.x & 31;
    float* p = out + (size_t)row * OUTD;

    float4 v = ((float4*)p)[lane];
    float m = fmaxf(fmaxf(v.x, v.y), fmaxf(v.z, v.w));
#pragma unroll
    for (int o = 16; o > 0; o >>= 1)
        m = fmaxf(m, __shfl_xor_sync(0xffffffffu, m, o));
    float s = expf(v.x - m) + expf(v.y - m) + expf(v.z - m) + expf(v.w - m);
#pragma unroll
    for (int o = 16; o > 0; o >>= 1)
        s += __shfl_xor_sync(0xffffffffu, s, o);
    const float lse = m + logf(s);
    v.x -= lse; v.y -= lse; v.z -= lse; v.w -= lse;
    ((float4*)p)[lane] = v;
}

// ---------------------------------------------------------------------------
extern "C" void kernel_launch(void* const* d_in, const int* in_sizes, int n_in,
                              void* d_out, int out_size)
{
    const float* seq  = (const float*)d_in[0];
    const float* Wih  = (const float*)d_in[1];
    const float* Whh  = (const float*)d_in[2];
    const float* bih  = (const float*)d_in[3];
    const float* bhh  = (const float*)d_in[4];
    const float* Wout = (const float*)d_in[5];
    const float* bout = (const float*)d_in[6];
    float* out = (float*)d_out;

    cudaFuncSetAttribute(lstm_tc_kernel,
                         cudaFuncAttributeMaxDynamicSharedMemorySize, SM_TOTAL);

    lstm_tc_kernel<<<NCTA, THREADS, SM_TOTAL>>>(seq, Wih, Whh, bih, bhh);
    head_kernel<<<NSTEP, 256>>>(Wout, bout, out);
    lsm_kernel<<<(BATCH * NSTEP) / 8, 256>>>(out);
}

// round 5
// speedup vs baseline: 4.0342x; 2.2815x over previous
#include <cuda_runtime.h>
#include <cuda_fp16.h>
#include <math.h>
#include <stdint.h>

#define BATCH 128
#define SEQT  1024
#define NSTEP 1023
#define IND   256
#define HID   1024
#define OUTD  128
#define NCTA  128

// ---- main-kernel SMEM layout (bytes) ----
#define W_BYTES 65536            // 64 k16-chunks x 4 gates x 256B fragments
#define AB0     65536            // A stage buf 0 (128 rows x 272B)
#define AB1     100352           // A stage buf 1
#define AROWB   272
#define GM0     65536            // gate-exchange matrices (alias A bufs)
#define GM1     83968
#define SM_MAIN 135168

// ---- gx kernel ----
#define GX_AROWB 528
#define GX_BOFF  67584
#define GX_SM    133120

// ---- head kernel ----
#define HD_AROWB 272
#define HD_BOFF  34816
#define HD_SM    67584

// Scratch (device globals — allocation inside kernel_launch is forbidden).
__device__ __half    g_hall[(size_t)NSTEP * BATCH * HID];       // h_t, f16 (~268 MB)
__device__ __half    g_gxb[(size_t)NSTEP * BATCH * 4 * HID];    // x-gates + biases (~1.07 GB)
__device__ unsigned  g_bar;

// ---------------------------------------------------------------------------
__device__ __forceinline__ void mma_f16(float* d, const uint32_t* a,
                                        uint32_t b0, uint32_t b1)
{
    asm volatile(
        "mma.sync.aligned.m16n8k16.row.col.f32.f16.f16.f32 "
        "{%0,%1,%2,%3}, {%4,%5,%6,%7}, {%8,%9}, {%0,%1,%2,%3};"
        : "+f"(d[0]), "+f"(d[1]), "+f"(d[2]), "+f"(d[3])
        : "r"(a[0]), "r"(a[1]), "r"(a[2]), "r"(a[3]), "r"(b0), "r"(b1));
}

// Replay-safe grid barrier (monotonic epoch counter; validated rounds 2/4).
__device__ __forceinline__ void grid_barrier()
{
    __syncthreads();
    if (threadIdx.x == 0) {
        __threadfence();
        unsigned old    = atomicAdd(&g_bar, 1u);
        unsigned target = (old / NCTA + 1u) * NCTA;
        unsigned cur;
        do {
            asm volatile("ld.acquire.gpu.u32 %0, [%1];" : "=r"(cur) : "l"(&g_bar));
        } while (cur < target);
    }
    __syncthreads();
}

// ---------------------------------------------------------------------------
// gx precompute: gxb[t][b][n] = x_t @ W_ih^T + b_ih + b_hh   (f16 out)
// grid (32 n-tiles, 1023 t), 512 threads. Warp (mg 0..3, ng 0..3): M32 x N32.
// ---------------------------------------------------------------------------
__global__ __launch_bounds__(512, 1) void gx_kernel(
    const float* __restrict__ seq, const float* __restrict__ Wih,
    const float* __restrict__ bih, const float* __restrict__ bhh)
{
    extern __shared__ __align__(16) char smem[];
    const int tid = threadIdx.x, warp = tid >> 5, lane = tid & 31;
    const int mg = warp & 3, ng = warp >> 2;
    const int tig = lane & 3, grp = lane >> 2;
    const int t = blockIdx.y, n0 = blockIdx.x * 128;

    // A = x_t [128 x 256] f32 -> f16, row stride 528B
#pragma unroll
    for (int i = 0; i < 16; i++) {
        const int idx4 = i * 512 + tid;
        const int row = idx4 >> 6, q = idx4 & 63;
        float4 v = *(const float4*)(seq + ((size_t)row * SEQT + t) * IND + q * 4);
        char* dst = smem + row * GX_AROWB + q * 8;
        *(__half2*)(dst)     = __floats2half2_rn(v.x, v.y);
        *(__half2*)(dst + 4) = __floats2half2_rn(v.z, v.w);
    }
    // B fragments: 16 chunks x 16 n-tiles x 256B
    {
        __half2* Bh = (__half2*)(smem + GX_BOFF);
        for (int idx = tid; idx < 16 * 16 * 32; idx += 512) {
            const int c = idx >> 9, nt = (idx >> 5) & 15, ln = idx & 31;
            const int n = n0 + nt * 8 + (ln >> 2);
            const float* wp = Wih + (size_t)n * IND + c * 16 + (ln & 3) * 2;
            Bh[(c * 16 + nt) * 64 + ln * 2 + 0] = __floats2half2_rn(wp[0], wp[1]);
            Bh[(c * 16 + nt) * 64 + ln * 2 + 1] = __floats2half2_rn(wp[8], wp[9]);
        }
    }
    __syncthreads();

    float acc[2][4][4];
#pragma unroll
    for (int mt = 0; mt < 2; mt++)
#pragma unroll
        for (int nt = 0; nt < 4; nt++)
#pragma unroll
            for (int j = 0; j < 4; j++) acc[mt][nt][j] = 0.f;

#pragma unroll
    for (int c = 0; c < 16; c++) {
        uint32_t a[2][4];
#pragma unroll
        for (int mt = 0; mt < 2; mt++) {
            const int ra = mg * 32 + mt * 16 + grp;
            const int off = ra * GX_AROWB + c * 32 + tig * 4;
            a[mt][0] = *(const uint32_t*)(smem + off);
            a[mt][2] = *(const uint32_t*)(smem + off + 16);
            a[mt][1] = *(const uint32_t*)(smem + off + 8 * GX_AROWB);
            a[mt][3] = *(const uint32_t*)(smem + off + 8 * GX_AROWB + 16);
        }
#pragma unroll
        for (int nt = 0; nt < 4; nt++) {
            uint2 b = *(const uint2*)(smem + GX_BOFF +
                        ((c * 16 + ng * 4 + nt) * 64 + lane * 2) * 4);
#pragma unroll
            for (int mt = 0; mt < 2; mt++) mma_f16(acc[mt][nt], a[mt], b.x, b.y);
        }
    }

    // epilogue: + biases, store f16
#pragma unroll
    for (int mt = 0; mt < 2; mt++) {
        const int ra = mg * 32 + mt * 16 + grp;
#pragma unroll
        for (int nt = 0; nt < 4; nt++) {
            const int col = ng * 32 + nt * 8 + tig * 2;
            const int ngl = n0 + col;
            const float b0 = bih[ngl] + bhh[ngl];
            const float b1 = bih[ngl + 1] + bhh[ngl + 1];
            __half* o0 = g_gxb + ((size_t)t * BATCH + ra) * (4 * HID) + ngl;
            __half* o1 = g_gxb + ((size_t)t * BATCH + ra + 8) * (4 * HID) + ngl;
            *(__half2*)o0 = __floats2half2_rn(acc[mt][nt][0] + b0, acc[mt][nt][1] + b1);
            *(__half2*)o1 = __floats2half2_rn(acc[mt][nt][2] + b0, acc[mt][nt][3] + b1);
        }
    }
}

// ---------------------------------------------------------------------------
// Persistent fp16 tensor-core LSTM. 128 CTAs x 512 threads.
// CTA owns 8 units = 32 gate cols (n = gate*8 + unit). Warp (mg,ng,kh):
// M32 (2 m16 tiles) x N16 (gates 2ng,2ng+1) x K-half. Weights resident
// in fragment order (64 KB). A = h_{t-1} f16, 8 stages of 128K, dbl-buffered.
// ---------------------------------------------------------------------------
__global__ __launch_bounds__(512, 1) void lstm_f16_kernel(const float* __restrict__ Whh)
{
    extern __shared__ __align__(16) char smem[];
    const int tid = threadIdx.x, warp = tid >> 5, lane = tid & 31;
    const int mg = warp & 3, ng = (warp >> 2) & 1, kh = warp >> 3;
    const int tig = lane & 3, grp = lane >> 2;
    const int cta = blockIdx.x;

    // resident weight fragments
    {
        __half2* Bw = (__half2*)smem;
        for (int idx = tid; idx < 64 * 4 * 32; idx += 512) {
            const int c = idx >> 7, g = (idx >> 5) & 3, ln = idx & 31;
            const float* wp = Whh + (size_t)(g * HID + 8 * cta + (ln >> 2)) * HID
                                  + c * 16 + (ln & 3) * 2;
            Bw[(c * 4 + g) * 64 + ln * 2 + 0] = __floats2half2_rn(wp[0], wp[1]);
            Bw[(c * 4 + g) * 64 + ln * 2 + 1] = __floats2half2_rn(wp[8], wp[9]);
        }
    }

    // cell-update ownership: thread -> (row, 2 units)
    const int urow = tid >> 2, um = tid & 3;
    float cst0 = 0.f, cst1 = 0.f;
    __syncthreads();

    for (int t = 0; t < NSTEP; t++) {
        float acc[2][2][4];
#pragma unroll
        for (int mt = 0; mt < 2; mt++)
#pragma unroll
            for (int nt = 0; nt < 2; nt++)
#pragma unroll
                for (int j = 0; j < 4; j++) acc[mt][nt][j] = 0.f;

        if (t > 0) {
            const __half* hsrc = g_hall + (size_t)(t - 1) * BATCH * HID;
            uint4 pf[4];
#pragma unroll
            for (int i = 0; i < 4; i++) {
                const int idx4 = i * 512 + tid;
                pf[i] = *(const uint4*)(hsrc + (size_t)(idx4 >> 4) * HID + (idx4 & 15) * 8);
            }
#pragma unroll
            for (int i = 0; i < 4; i++) {
                const int idx4 = i * 512 + tid;
                *(uint4*)(smem + AB0 + (idx4 >> 4) * AROWB + (idx4 & 15) * 16) = pf[i];
            }
            __syncthreads();

            for (int s = 0; s < 8; s++) {
                if (s < 7) {
#pragma unroll
                    for (int i = 0; i < 4; i++) {
                        const int idx4 = i * 512 + tid;
                        pf[i] = *(const uint4*)(hsrc + (size_t)(idx4 >> 4) * HID
                                                + (s + 1) * 128 + (idx4 & 15) * 8);
                    }
                }
                const char* Ab = smem + ((s & 1) ? AB1 : AB0);
#pragma unroll
                for (int c4 = 0; c4 < 4; c4++) {
                    const int lc = kh * 4 + c4;        // chunk within stage
                    const int cg = s * 8 + lc;         // global k16-chunk
                    uint32_t a[2][4];
#pragma unroll
                    for (int mt = 0; mt < 2; mt++) {
                        const int ra = mg * 32 + mt * 16 + grp;
                        const int off = ra * AROWB + lc * 32 + tig * 4;
                        a[mt][0] = *(const uint32_t*)(Ab + off);
                        a[mt][2] = *(const uint32_t*)(Ab + off + 16);
                        a[mt][1] = *(const uint32_t*)(Ab + off + 8 * AROWB);
                        a[mt][3] = *(const uint32_t*)(Ab + off + 8 * AROWB + 16);
                    }
#pragma unroll
                    for (int nt = 0; nt < 2; nt++) {
                        const int g = ng * 2 + nt;
                        uint2 b = *(const uint2*)(smem + ((cg * 4 + g) * 64 + lane * 2) * 4);
#pragma unroll
                        for (int mt = 0; mt < 2; mt++)
                            mma_f16(acc[mt][nt], a[mt], b.x, b.y);
                    }
                }
                if (s < 7) {
                    char* An = smem + (((s + 1) & 1) ? AB1 : AB0);
#pragma unroll
                    for (int i = 0; i < 4; i++) {
                        const int idx4 = i * 512 + tid;
                        *(uint4*)(An + (idx4 >> 4) * AROWB + (idx4 & 15) * 16) = pf[i];
                    }
                }
                __syncthreads();
            }

            // gate-matrix exchange (kh partials kept separate, summed in pass C)
            float* gm = (float*)(smem + (kh ? GM1 : GM0));
#pragma unroll
            for (int mt = 0; mt < 2; mt++) {
                const int ra = mg * 32 + mt * 16 + grp;
#pragma unroll
                for (int nt = 0; nt < 2; nt++) {
                    const int col = (ng * 2 + nt) * 8 + tig * 2;
                    *(float2*)(gm + ra * 36 + col) =
                        make_float2(acc[mt][nt][0], acc[mt][nt][1]);
                    *(float2*)(gm + (ra + 8) * 36 + col) =
                        make_float2(acc[mt][nt][2], acc[mt][nt][3]);
                }
            }
            __syncthreads();
        }

        // pass C: every thread updates (urow, units 2um, 2um+1)
        const float* gm0 = (const float*)(smem + GM0);
        const float* gm1 = (const float*)(smem + GM1);
        const __half* gxb = g_gxb + ((size_t)t * BATCH + urow) * (4 * HID)
                                  + 8 * cta + 2 * um;
        float gg[4][2];
#pragma unroll
        for (int g = 0; g < 4; g++) {
            float2 xf = __half22float2(*(const __half2*)(gxb + g * HID));
            if (t > 0) {
                const int col = g * 8 + 2 * um;
                float2 v0 = *(const float2*)(gm0 + urow * 36 + col);
                float2 v1 = *(const float2*)(gm1 + urow * 36 + col);
                gg[g][0] = v0.x + v1.x + xf.x;
                gg[g][1] = v0.y + v1.y + xf.y;
            } else { gg[g][0] = xf.x; gg[g][1] = xf.y; }
        }
        float h0, h1;
        {
            const float si = 1.f / (1.f + expf(-gg[0][0]));
            const float sf = 1.f / (1.f + expf(-gg[1][0]));
            const float tg = tanhf(gg[2][0]);
            const float so = 1.f / (1.f + expf(-gg[3][0]));
            cst0 = sf * cst0 + si * tg;
            h0 = so * tanhf(cst0);
        }
        {
            const float si = 1.f / (1.f + expf(-gg[0][1]));
            const float sf = 1.f / (1.f + expf(-gg[1][1]));
            const float tg = tanhf(gg[2][1]);
            const float so = 1.f / (1.f + expf(-gg[3][1]));
            cst1 = sf * cst1 + si * tg;
            h1 = so * tanhf(cst1);
        }
        *(__half2*)(g_hall + ((size_t)t * BATCH + urow) * HID + 8 * cta + 2 * um) =
            __floats2half2_rn(h0, h1);

        grid_barrier();
    }
}

// ---------------------------------------------------------------------------
// Head GEMM (fp16 mma): logits[b][t][v] = h_t[b].Wout[v] + bout[v].
// grid 1023 (t), 512 threads; warp (mg 0..3, ng 0..3): M32 x N32; K staged 8x128.
// ---------------------------------------------------------------------------
__global__ __launch_bounds__(512, 1) void head_kernel(
    const float* __restrict__ Wout, const float* __restrict__ bout,
    float* __restrict__ out)
{
    extern __shared__ __align__(16) char smem[];
    const int tid = threadIdx.x, warp = tid >> 5, lane = tid & 31;
    const int mg = warp & 3, ng = warp >> 2;
    const int tig = lane & 3, grp = lane >> 2;
    const int t = blockIdx.x;

    float acc[2][4][4];
#pragma unroll
    for (int mt = 0; mt < 2; mt++)
#pragma unroll
        for (int nt = 0; nt < 4; nt++)
#pragma unroll
            for (int j = 0; j < 4; j++) acc[mt][nt][j] = 0.f;

    for (int s = 0; s < 8; s++) {
#pragma unroll
        for (int i = 0; i < 4; i++) {
            const int idx4 = i * 512 + tid;
            *(uint4*)(smem + (idx4 >> 4) * HD_AROWB + (idx4 & 15) * 16) =
                *(const uint4*)(g_hall + ((size_t)t * BATCH + (idx4 >> 4)) * HID
                                + s * 128 + (idx4 & 15) * 8);
        }
        {
            __half2* Bh = (__half2*)(smem + HD_BOFF);
            for (int idx = tid; idx < 8 * 16 * 32; idx += 512) {
                const int c = idx >> 9, nt = (idx >> 5) & 15, ln = idx & 31;
                const int n = nt * 8 + (ln >> 2);
                const float* wp = Wout + (size_t)n * HID + s * 128 + c * 16 + (ln & 3) * 2;
                Bh[(c * 16 + nt) * 64 + ln * 2 + 0] = __floats2half2_rn(wp[0], wp[1]);
                Bh[(c * 16 + nt) * 64 + ln * 2 + 1] = __floats2half2_rn(wp[8], wp[9]);
            }
        }
        __syncthreads();
#pragma unroll
        for (int c = 0; c < 8; c++) {
            uint32_t a[2][4];
#pragma unroll
            for (int mt = 0; mt < 2; mt++) {
                const int ra = mg * 32 + mt * 16 + grp;
                const int off = ra * HD_AROWB + c * 32 + tig * 4;
                a[mt][0] = *(const uint32_t*)(smem + off);
                a[mt][2] = *(const uint32_t*)(smem + off + 16);
                a[mt][1] = *(const uint32_t*)(smem + off + 8 * HD_AROWB);
                a[mt][3] = *(const uint32_t*)(smem + off + 8 * HD_AROWB + 16);
            }
#pragma unroll
            for (int nt = 0; nt < 4; nt++) {
                uint2 b = *(const uint2*)(smem + HD_BOFF +
                            ((c * 16 + ng * 4 + nt) * 64 + lane * 2) * 4);
#pragma unroll
                for (int mt = 0; mt < 2; mt++) mma_f16(acc[mt][nt], a[mt], b.x, b.y);
            }
        }
        __syncthreads();
    }

#pragma unroll
    for (int mt = 0; mt < 2; mt++) {
        const int ra = mg * 32 + mt * 16 + grp;
#pragma unroll
        for (int nt = 0; nt < 4; nt++) {
            const int col = ng * 32 + nt * 8 + tig * 2;
            const float b0 = bout[col], b1 = bout[col + 1];
            *(float2*)(out + ((size_t)ra * NSTEP + t) * OUTD + col) =
                make_float2(acc[mt][nt][0] + b0, acc[mt][nt][1] + b1);
            *(float2*)(out + ((size_t)(ra + 8) * NSTEP + t) * OUTD + col) =
                make_float2(acc[mt][nt][2] + b0, acc[mt][nt][3] + b1);
        }
    }
}

// ---------------------------------------------------------------------------
// In-place log-softmax: one warp per 128-wide row.
// ---------------------------------------------------------------------------
__global__ __launch_bounds__(256) void lsm_kernel(float* __restrict__ out)
{
    const int row  = (blockIdx.x * 256 + threadIdx.x) >> 5;
    const int lane = threadIdx.x & 31;
    float* p = out + (size_t)row * OUTD;

    float4 v = ((float4*)p)[lane];
    float m = fmaxf(fmaxf(v.x, v.y), fmaxf(v.z, v.w));
#pragma unroll
    for (int o = 16; o > 0; o >>= 1)
        m = fmaxf(m, __shfl_xor_sync(0xffffffffu, m, o));
    float s = expf(v.x - m) + expf(v.y - m) + expf(v.z - m) + expf(v.w - m);
#pragma unroll
    for (int o = 16; o > 0; o >>= 1)
        s += __shfl_xor_sync(0xffffffffu, s, o);
    const float lse = m + logf(s);
    v.x -= lse; v.y -= lse; v.z -= lse; v.w -= lse;
    ((float4*)p)[lane] = v;
}

// ---------------------------------------------------------------------------
extern "C" void kernel_launch(void* const* d_in, const int* in_sizes, int n_in,
                              void* d_out, int out_size)
{
    const float* seq  = (const float*)d_in[0];
    const float* Wih  = (const float*)d_in[1];
    const float* Whh  = (const float*)d_in[2];
    const float* bih  = (const float*)d_in[3];
    const float* bhh  = (const float*)d_in[4];
    const float* Wout = (const float*)d_in[5];
    const float* bout = (const float*)d_in[6];
    float* out = (float*)d_out;

    cudaFuncSetAttribute(gx_kernel,       cudaFuncAttributeMaxDynamicSharedMemorySize, GX_SM);
    cudaFuncSetAttribute(lstm_f16_kernel, cudaFuncAttributeMaxDynamicSharedMemorySize, SM_MAIN);
    cudaFuncSetAttribute(head_kernel,     cudaFuncAttributeMaxDynamicSharedMemorySize, HD_SM);

    gx_kernel<<<dim3(32, NSTEP), 512, GX_SM>>>(seq, Wih, bih, bhh);
    lstm_f16_kernel<<<NCTA, 512, SM_MAIN>>>(Whh);
    head_kernel<<<NSTEP, 512, HD_SM>>>(Wout, bout, out);
    lsm_kernel<<<(BATCH * NSTEP) / 8, 256>>>(out);
}

// round 6
// speedup vs baseline: 4.4400x; 1.1006x over previous
#include <cuda_runtime.h>
#include <cuda_fp16.h>
#include <math.h>
#include <stdint.h>

#define BATCH 128
#define SEQT  1024
#define NSTEP 1023
#define IND   256
#define HID   1024
#define OUTD  128
#define NCTA  128

// ---- main-kernel SMEM layout (bytes) ----
#define AB0     65536            // A stage buf 0 (128 rows x 272B)
#define AB1     100352           // A stage buf 1
#define AROWB   272
#define GMOFF   65536            // 4 gate-partial matrices (alias A bufs; used post-stages)
#define GMSZ    18432            // 128 rows x 36 floats
#define SM_MAIN 139264

// ---- gx kernel ----
#define GX_AROWB 528
#define GX_BOFF  67584
#define GX_SM    133120

// ---- head kernel ----
#define HD_AROWB 272
#define HD_BOFF  34816
#define HD_SM    67584

// Scratch (device globals — allocation inside kernel_launch is forbidden).
__device__ __half    g_hall[(size_t)NSTEP * BATCH * HID];       // h_t, f16 (~268 MB)
__device__ __half    g_gxb[(size_t)NSTEP * BATCH * 4 * HID];    // x-gates + biases (~1.07 GB)
__device__ unsigned  g_bar;

// ---------------------------------------------------------------------------
__device__ __forceinline__ void mma_f16(float* d, const uint32_t* a,
                                        uint32_t b0, uint32_t b1)
{
    asm volatile(
        "mma.sync.aligned.m16n8k16.row.col.f32.f16.f16.f32 "
        "{%0,%1,%2,%3}, {%4,%5,%6,%7}, {%8,%9}, {%0,%1,%2,%3};"
        : "+f"(d[0]), "+f"(d[1]), "+f"(d[2]), "+f"(d[3])
        : "r"(a[0]), "r"(a[1]), "r"(a[2]), "r"(a[3]), "r"(b0), "r"(b1));
}

// Fast sigmoid/tanh: ex2.approx + rcp.approx (~1e-7 rel err, ~4 instr).
__device__ __forceinline__ float sigmoid_f(float x)
{
    float e, r;
    asm("ex2.approx.f32 %0, %1;" : "=f"(e) : "f"(-1.4426950408889634f * x));
    asm("rcp.approx.f32 %0, %1;" : "=f"(r) : "f"(1.0f + e));
    return r;
}
__device__ __forceinline__ float tanh_f(float x)
{
    return 2.0f * sigmoid_f(2.0f * x) - 1.0f;
}

// Replay-safe grid barrier (monotonic epoch counter; validated rounds 2/4/5).
__device__ __forceinline__ void grid_barrier()
{
    __syncthreads();
    if (threadIdx.x == 0) {
        __threadfence();
        unsigned old    = atomicAdd(&g_bar, 1u);
        unsigned target = (old / NCTA + 1u) * NCTA;
        unsigned cur;
        do {
            asm volatile("ld.acquire.gpu.u32 %0, [%1];" : "=r"(cur) : "l"(&g_bar));
        } while (cur < target);
    }
    __syncthreads();
}

// ---------------------------------------------------------------------------
// gx precompute: gxb[t][b][n] = x_t @ W_ih^T + b_ih + b_hh   (f16 out)
// ---------------------------------------------------------------------------
__global__ __launch_bounds__(512, 1) void gx_kernel(
    const float* __restrict__ seq, const float* __restrict__ Wih,
    const float* __restrict__ bih, const float* __restrict__ bhh)
{
    extern __shared__ __align__(16) char smem[];
    const int tid = threadIdx.x, warp = tid >> 5, lane = tid & 31;
    const int mg = warp & 3, ng = warp >> 2;
    const int tig = lane & 3, grp = lane >> 2;
    const int t = blockIdx.y, n0 = blockIdx.x * 128;

#pragma unroll
    for (int i = 0; i < 16; i++) {
        const int idx4 = i * 512 + tid;
        const int row = idx4 >> 6, q = idx4 & 63;
        float4 v = *(const float4*)(seq + ((size_t)row * SEQT + t) * IND + q * 4);
        char* dst = smem + row * GX_AROWB + q * 8;
        *(__half2*)(dst)     = __floats2half2_rn(v.x, v.y);
        *(__half2*)(dst + 4) = __floats2half2_rn(v.z, v.w);
    }
    {
        __half2* Bh = (__half2*)(smem + GX_BOFF);
        for (int idx = tid; idx < 16 * 16 * 32; idx += 512) {
            const int c = idx >> 9, nt = (idx >> 5) & 15, ln = idx & 31;
            const int n = n0 + nt * 8 + (ln >> 2);
            const float* wp = Wih + (size_t)n * IND + c * 16 + (ln & 3) * 2;
            Bh[(c * 16 + nt) * 64 + ln * 2 + 0] = __floats2half2_rn(wp[0], wp[1]);
            Bh[(c * 16 + nt) * 64 + ln * 2 + 1] = __floats2half2_rn(wp[8], wp[9]);
        }
    }
    __syncthreads();

    float acc[2][4][4];
#pragma unroll
    for (int mt = 0; mt < 2; mt++)
#pragma unroll
        for (int nt = 0; nt < 4; nt++)
#pragma unroll
            for (int j = 0; j < 4; j++) acc[mt][nt][j] = 0.f;

#pragma unroll
    for (int c = 0; c < 16; c++) {
        uint32_t a[2][4];
#pragma unroll
        for (int mt = 0; mt < 2; mt++) {
            const int ra = mg * 32 + mt * 16 + grp;
            const int off = ra * GX_AROWB + c * 32 + tig * 4;
            a[mt][0] = *(const uint32_t*)(smem + off);
            a[mt][2] = *(const uint32_t*)(smem + off + 16);
            a[mt][1] = *(const uint32_t*)(smem + off + 8 * GX_AROWB);
            a[mt][3] = *(const uint32_t*)(smem + off + 8 * GX_AROWB + 16);
        }
#pragma unroll
        for (int nt = 0; nt < 4; nt++) {
            uint2 b = *(const uint2*)(smem + GX_BOFF +
                        ((c * 16 + ng * 4 + nt) * 64 + lane * 2) * 4);
#pragma unroll
            for (int mt = 0; mt < 2; mt++) mma_f16(acc[mt][nt], a[mt], b.x, b.y);
        }
    }

#pragma unroll
    for (int mt = 0; mt < 2; mt++) {
        const int ra = mg * 32 + mt * 16 + grp;
#pragma unroll
        for (int nt = 0; nt < 4; nt++) {
            const int col = ng * 32 + nt * 8 + tig * 2;
            const int ngl = n0 + col;
            const float b0 = bih[ngl] + bhh[ngl];
            const float b1 = bih[ngl + 1] + bhh[ngl + 1];
            __half* o0 = g_gxb + ((size_t)t * BATCH + ra) * (4 * HID) + ngl;
            __half* o1 = g_gxb + ((size_t)t * BATCH + ra + 8) * (4 * HID) + ngl;
            *(__half2*)o0 = __floats2half2_rn(acc[mt][nt][0] + b0, acc[mt][nt][1] + b1);
            *(__half2*)o1 = __floats2half2_rn(acc[mt][nt][2] + b0, acc[mt][nt][3] + b1);
        }
    }
}

// ---------------------------------------------------------------------------
// Persistent fp16 LSTM. 128 CTAs x 512 threads. CTA owns 8 units = 32 gate
// cols (n = gate*8 + unit). Warp (mg 0..3, kh 0..3): M32 x N32 x K256 —
// each warp covers ALL 32 N cols (A fragments read exactly once per step).
// A = h_{t-1} f16, 8 stages of 128K double-buffered; warp kh does chunks
// 2kh, 2kh+1 of each stage; 4 K-partials reduced via smem gm (aliased
// over the A stage buffers, which are dead by then).
// ---------------------------------------------------------------------------
__global__ __launch_bounds__(512, 1) void lstm_f16_kernel(const float* __restrict__ Whh)
{
    extern __shared__ __align__(16) char smem[];
    const int tid = threadIdx.x, warp = tid >> 5, lane = tid & 31;
    const int mg = warp & 3, kh = warp >> 2;
    const int tig = lane & 3, grp = lane >> 2;
    const int cta = blockIdx.x;

    // resident weight fragments: 64 k16-chunks x 4 gates x 256B
    {
        __half2* Bw = (__half2*)smem;
        for (int idx = tid; idx < 64 * 4 * 32; idx += 512) {
            const int c = idx >> 7, g = (idx >> 5) & 3, ln = idx & 31;
            const float* wp = Whh + (size_t)(g * HID + 8 * cta + (ln >> 2)) * HID
                                  + c * 16 + (ln & 3) * 2;
            Bw[(c * 4 + g) * 64 + ln * 2 + 0] = __floats2half2_rn(wp[0], wp[1]);
            Bw[(c * 4 + g) * 64 + ln * 2 + 1] = __floats2half2_rn(wp[8], wp[9]);
        }
    }

    const int urow = tid >> 2, um = tid & 3;   // cell-update ownership
    float cst0 = 0.f, cst1 = 0.f;
    __syncthreads();

    for (int t = 0; t < NSTEP; t++) {
        // prefetch gxb early (DRAM latency hidden behind the MMA stages)
        __half2 gx[4];
        {
            const __half* gxp = g_gxb + ((size_t)t * BATCH + urow) * (4 * HID)
                                      + 8 * cta + 2 * um;
#pragma unroll
            for (int g = 0; g < 4; g++) gx[g] = *(const __half2*)(gxp + (size_t)g * HID);
        }

        if (t > 0) {
            float acc[2][4][4];
#pragma unroll
            for (int mt = 0; mt < 2; mt++)
#pragma unroll
                for (int g = 0; g < 4; g++)
#pragma unroll
                    for (int j = 0; j < 4; j++) acc[mt][g][j] = 0.f;

            const __half* hsrc = g_hall + (size_t)(t - 1) * BATCH * HID;
            uint4 pf[4];
#pragma unroll
            for (int i = 0; i < 4; i++) {
                const int idx4 = i * 512 + tid;
                pf[i] = *(const uint4*)(hsrc + (size_t)(idx4 >> 4) * HID + (idx4 & 15) * 8);
            }
#pragma unroll
            for (int i = 0; i < 4; i++) {
                const int idx4 = i * 512 + tid;
                *(uint4*)(smem + AB0 + (idx4 >> 4) * AROWB + (idx4 & 15) * 16) = pf[i];
            }
            __syncthreads();

            for (int s = 0; s < 8; s++) {
                if (s < 7) {
#pragma unroll
                    for (int i = 0; i < 4; i++) {
                        const int idx4 = i * 512 + tid;
                        pf[i] = *(const uint4*)(hsrc + (size_t)(idx4 >> 4) * HID
                                                + (s + 1) * 128 + (idx4 & 15) * 8);
                    }
                }
                const char* Ab = smem + ((s & 1) ? AB1 : AB0);
#pragma unroll
                for (int c2 = 0; c2 < 2; c2++) {
                    const int lc = kh * 2 + c2;        // chunk within stage
                    const int cg = s * 8 + lc;         // global k16-chunk
                    uint32_t a[2][4];
#pragma unroll
                    for (int mt = 0; mt < 2; mt++) {
                        const int ra = mg * 32 + mt * 16 + grp;
                        const int off = ra * AROWB + lc * 32 + tig * 4;
                        a[mt][0] = *(const uint32_t*)(Ab + off);
                        a[mt][2] = *(const uint32_t*)(Ab + off + 16);
                        a[mt][1] = *(const uint32_t*)(Ab + off + 8 * AROWB);
                        a[mt][3] = *(const uint32_t*)(Ab + off + 8 * AROWB + 16);
                    }
#pragma unroll
                    for (int g = 0; g < 4; g++) {
                        uint2 b = *(const uint2*)(smem + ((cg * 4 + g) * 64 + lane * 2) * 4);
#pragma unroll
                        for (int mt = 0; mt < 2; mt++)
                            mma_f16(acc[mt][g], a[mt], b.x, b.y);
                    }
                }
                if (s < 7) {
                    char* An = smem + (((s + 1) & 1) ? AB1 : AB0);
#pragma unroll
                    for (int i = 0; i < 4; i++) {
                        const int idx4 = i * 512 + tid;
                        *(uint4*)(An + (idx4 >> 4) * AROWB + (idx4 & 15) * 16) = pf[i];
                    }
                }
                __syncthreads();
            }

            // gate-partial exchange: gm[kh][128 x 32] f32 (aliases A bufs)
            float* gm = (float*)(smem + GMOFF + kh * GMSZ);
#pragma unroll
            for (int mt = 0; mt < 2; mt++) {
                const int ra = mg * 32 + mt * 16 + grp;
#pragma unroll
                for (int g = 0; g < 4; g++) {
                    const int col = g * 8 + tig * 2;
                    *(float2*)(gm + ra * 36 + col) =
                        make_float2(acc[mt][g][0], acc[mt][g][1]);
                    *(float2*)(gm + (ra + 8) * 36 + col) =
                        make_float2(acc[mt][g][2], acc[mt][g][3]);
                }
            }
            __syncthreads();
        }

        // pass C: thread updates (urow, units 2um, 2um+1)
        float gg[4][2];
#pragma unroll
        for (int g = 0; g < 4; g++) {
            float2 xf = __half22float2(gx[g]);
            float s0 = xf.x, s1 = xf.y;
            if (t > 0) {
                const int col = g * 8 + 2 * um;
#pragma unroll
                for (int k = 0; k < 4; k++) {
                    const float* gm = (const float*)(smem + GMOFF + k * GMSZ);
                    float2 v = *(const float2*)(gm + urow * 36 + col);
                    s0 += v.x; s1 += v.y;
                }
            }
            gg[g][0] = s0; gg[g][1] = s1;
        }
        float h0, h1;
        {
            const float si = sigmoid_f(gg[0][0]);
            const float sf = sigmoid_f(gg[1][0]);
            const float tg = tanh_f(gg[2][0]);
            const float so = sigmoid_f(gg[3][0]);
            cst0 = sf * cst0 + si * tg;
            h0 = so * tanh_f(cst0);
        }
        {
            const float si = sigmoid_f(gg[0][1]);
            const float sf = sigmoid_f(gg[1][1]);
            const float tg = tanh_f(gg[2][1]);
            const float so = sigmoid_f(gg[3][1]);
            cst1 = sf * cst1 + si * tg;
            h1 = so * tanh_f(cst1);
        }
        *(__half2*)(g_hall + ((size_t)t * BATCH + urow) * HID + 8 * cta + 2 * um) =
            __floats2half2_rn(h0, h1);

        grid_barrier();
    }
}

// ---------------------------------------------------------------------------
// Head GEMM (fp16 mma): logits[b][t][v] = h_t[b].Wout[v] + bout[v].
// ---------------------------------------------------------------------------
__global__ __launch_bounds__(512, 1) void head_kernel(
    const float* __restrict__ Wout, const float* __restrict__ bout,
    float* __restrict__ out)
{
    extern __shared__ __align__(16) char smem[];
    const int tid = threadIdx.x, warp = tid >> 5, lane = tid & 31;
    const int mg = warp & 3, ng = warp >> 2;
    const int tig = lane & 3, grp = lane >> 2;
    const int t = blockIdx.x;

    float acc[2][4][4];
#pragma unroll
    for (int mt = 0; mt < 2; mt++)
#pragma unroll
        for (int nt = 0; nt < 4; nt++)
#pragma unroll
            for (int j = 0; j < 4; j++) acc[mt][nt][j] = 0.f;

    for (int s = 0; s < 8; s++) {
#pragma unroll
        for (int i = 0; i < 4; i++) {
            const int idx4 = i * 512 + tid;
            *(uint4*)(smem + (idx4 >> 4) * HD_AROWB + (idx4 & 15) * 16) =
                *(const uint4*)(g_hall + ((size_t)t * BATCH + (idx4 >> 4)) * HID
                                + s * 128 + (idx4 & 15) * 8);
        }
        {
            __half2* Bh = (__half2*)(smem + HD_BOFF);
            for (int idx = tid; idx < 8 * 16 * 32; idx += 512) {
                const int c = idx >> 9, nt = (idx >> 5) & 15, ln = idx & 31;
                const int n = nt * 8 + (ln >> 2);
                const float* wp = Wout + (size_t)n * HID + s * 128 + c * 16 + (ln & 3) * 2;
                Bh[(c * 16 + nt) * 64 + ln * 2 + 0] = __floats2half2_rn(wp[0], wp[1]);
                Bh[(c * 16 + nt) * 64 + ln * 2 + 1] = __floats2half2_rn(wp[8], wp[9]);
            }
        }
        __syncthreads();
#pragma unroll
        for (int c = 0; c < 8; c++) {
            uint32_t a[2][4];
#pragma unroll
            for (int mt = 0; mt < 2; mt++) {
                const int ra = mg * 32 + mt * 16 + grp;
                const int off = ra * HD_AROWB + c * 32 + tig * 4;
                a[mt][0] = *(const uint32_t*)(smem + off);
                a[mt][2] = *(const uint32_t*)(smem + off + 16);
                a[mt][1] = *(const uint32_t*)(smem + off + 8 * HD_AROWB);
                a[mt][3] = *(const uint32_t*)(smem + off + 8 * HD_AROWB + 16);
            }
#pragma unroll
            for (int nt = 0; nt < 4; nt++) {
                uint2 b = *(const uint2*)(smem + HD_BOFF +
                            ((c * 16 + ng * 4 + nt) * 64 + lane * 2) * 4);
#pragma unroll
                for (int mt = 0; mt < 2; mt++) mma_f16(acc[mt][nt], a[mt], b.x, b.y);
            }
        }
        __syncthreads();
    }

#pragma unroll
    for (int mt = 0; mt < 2; mt++) {
        const int ra = mg * 32 + mt * 16 + grp;
#pragma unroll
        for (int nt = 0; nt < 4; nt++) {
            const int col = ng * 32 + nt * 8 + tig * 2;
            const float b0 = bout[col], b1 = bout[col + 1];
            *(float2*)(out + ((size_t)ra * NSTEP + t) * OUTD + col) =
                make_float2(acc[mt][nt][0] + b0, acc[mt][nt][1] + b1);
            *(float2*)(out + ((size_t)(ra + 8) * NSTEP + t) * OUTD + col) =
                make_float2(acc[mt][nt][2] + b0, acc[mt][nt][3] + b1);
        }
    }
}

// ---------------------------------------------------------------------------
// In-place log-softmax: one warp per 128-wide row.
// ---------------------------------------------------------------------------
__global__ __launch_bounds__(256) void lsm_kernel(float* __restrict__ out)
{
    const int row  = (blockIdx.x * 256 + threadIdx.x) >> 5;
    const int lane = threadIdx.x & 31;
    float* p = out + (size_t)row * OUTD;

    float4 v = ((float4*)p)[lane];
    float m = fmaxf(fmaxf(v.x, v.y), fmaxf(v.z, v.w));
#pragma unroll
    for (int o = 16; o > 0; o >>= 1)
        m = fmaxf(m, __shfl_xor_sync(0xffffffffu, m, o));
    float s = expf(v.x - m) + expf(v.y - m) + expf(v.z - m) + expf(v.w - m);
#pragma unroll
    for (int o = 16; o > 0; o >>= 1)
        s += __shfl_xor_sync(0xffffffffu, s, o);
    const float lse = m + logf(s);
    v.x -= lse; v.y -= lse; v.z -= lse; v.w -= lse;
    ((float4*)p)[lane] = v;
}

// ---------------------------------------------------------------------------
extern "C" void kernel_launch(void* const* d_in, const int* in_sizes, int n_in,
                              void* d_out, int out_size)
{
    const float* seq  = (const float*)d_in[0];
    const float* Wih  = (const float*)d_in[1];
    const float* Whh  = (const float*)d_in[2];
    const float* bih  = (const float*)d_in[3];
    const float* bhh  = (const float*)d_in[4];
    const float* Wout = (const float*)d_in[5];
    const float* bout = (const float*)d_in[6];
    float* out = (float*)d_out;

    cudaFuncSetAttribute(gx_kernel,       cudaFuncAttributeMaxDynamicSharedMemorySize, GX_SM);
    cudaFuncSetAttribute(lstm_f16_kernel, cudaFuncAttributeMaxDynamicSharedMemorySize, SM_MAIN);
    cudaFuncSetAttribute(head_kernel,     cudaFuncAttributeMaxDynamicSharedMemorySize, HD_SM);

    gx_kernel<<<dim3(32, NSTEP), 512, GX_SM>>>(seq, Wih, bih, bhh);
    lstm_f16_kernel<<<NCTA, 512, SM_MAIN>>>(Whh);
    head_kernel<<<NSTEP, 512, HD_SM>>>(Wout, bout, out);
    lsm_kernel<<<(BATCH * NSTEP) / 8, 256>>>(out);
}